// round 11
// baseline (speedup 1.0000x reference)
#include <cuda_runtime.h>
#include <cuda_fp16.h>

#define SKPAD 208

__device__ float g_M[64 * 256];                   // folded Q*K, 64 KB
__device__ unsigned long long g_arrivals = 0;     // monotonic
__device__ unsigned long long g_done = 0;         // monotonic, +4 per launch

typedef unsigned long long ull;

// ---- packed fp32x2 helpers ----
__device__ __forceinline__ ull fma2(ull a, ull b, ull c) {
    ull d;
    asm("fma.rn.f32x2 %0, %1, %2, %3;" : "=l"(d) : "l"(a), "l"(b), "l"(c));
    return d;
}
__device__ __forceinline__ ull add2(ull a, ull b) {
    ull d;
    asm("add.rn.f32x2 %0, %1, %2;" : "=l"(d) : "l"(a), "l"(b));
    return d;
}
__device__ __forceinline__ ull pack2(float x, float y) {
    ull r;
    asm("mov.b64 %0, {%1, %2};" : "=l"(r) : "f"(x), "f"(y));
    return r;
}
__device__ __forceinline__ float2 unpack2(ull a) {
    float2 f;
    asm("mov.b64 {%0, %1}, %2;" : "=f"(f.x), "=f"(f.y) : "l"(a));
    return f;
}
__device__ __forceinline__ ull h2f2(unsigned h) {
    ull r;
    asm("{\n\t.reg .b16 lo, hi;\n\t.reg .f32 flo, fhi;\n\t"
        "mov.b32 {lo, hi}, %1;\n\t"
        "cvt.f32.f16 flo, lo;\n\tcvt.f32.f16 fhi, hi;\n\t"
        "mov.b64 %0, {flo, fhi};\n\t}" : "=l"(r) : "r"(h));
    return r;
}
__device__ __forceinline__ ull ld_acq(const ull* p) {
    ull v;
    asm volatile("ld.global.acquire.gpu.u64 %0, [%1];" : "=l"(v) : "l"(p) : "memory");
    return v;
}

#define SA_BYTES   (SKPAD * 128)              // 26624: fp16 swizzled tile (aliased later)
#define SW_OFF     SA_BYTES                   // 1024: W row, later ctx
#define SC_OFF     (SW_OFF + 1024)            // 3328: packed scores ull[2][SKPAD]
#define SINV_OFF   (SC_OFF + 3328)            // 32
#define SQ_OFF     (SINV_OFF + 32)            // 256: q row
#define SMEM_BYTES (SQ_OFF + 256)             // 31264

extern __shared__ char s_raw[];

__global__ __launch_bounds__(128, 7) void k_all(
    const float* __restrict__ query, const float* __restrict__ Qm,
    const float* __restrict__ Km,    const float* __restrict__ act,
    const float* __restrict__ V,     float* __restrict__ out,
    int nsk, int B) {

    __shared__ ull s_gen;
    int t = threadIdx.x;

    if (t == 0) {
        ull old = atomicAdd(&g_arrivals, 1ULL);
        s_gen = old / (ull)gridDim.x;
    }
    __syncthreads();
    ull gen = s_gen;

    // ===================== 4 M-producer CTAs (one per head) =====================
    if (blockIdx.x < 4) {
        int h = blockIdx.x;
        float* sQh = (float*)s_raw;           // 64 x 16
        float* sKh = (float*)(s_raw + 4096);  // 64 x 16
        for (int idx = t; idx < 1024; idx += 128) {
            int r = idx >> 4, j = idx & 15;
            sQh[idx] = Qm[r * 64 + h * 16 + j];
            sKh[idx] = Km[r * 64 + h * 16 + j];
        }
        __syncthreads();

        int i = t >> 1, half = t & 1;
        const ull* qrow = (const ull*)(sQh + i * 16);
        ull q[8];
#pragma unroll
        for (int k = 0; k < 8; k++) q[k] = qrow[k];
        float accv[32];
#pragma unroll 4
        for (int aa = 0; aa < 32; aa++) {
            int a = half * 32 + aa;
            const ull* krow = (const ull*)(sKh + a * 16);
            ull s = 0ull;
#pragma unroll
            for (int k = 0; k < 8; k++) s = fma2(q[k], krow[k], s);
            float2 f = unpack2(s);
            accv[aa] = 0.125f * (f.x + f.y);
        }
        float4* dst = (float4*)(g_M + i * 256 + h * 64 + half * 32);
#pragma unroll
        for (int v = 0; v < 8; v++)
            dst[v] = make_float4(accv[4 * v], accv[4 * v + 1],
                                 accv[4 * v + 2], accv[4 * v + 3]);
        __threadfence();
        __syncthreads();
        if (t == 0) atomicAdd(&g_done, 1ULL);
        return;
    }

    // ===================== batch CTAs =====================
    int b = blockIdx.x - 4;

    char*  sab   = s_raw;
    float* sw    = (float*)(s_raw + SW_OFF);
    ull*   scu   = (ull*)(s_raw + SC_OFF);
    float* sinv  = (float*)(s_raw + SINV_OFF);
    float* sq    = (float*)(s_raw + SQ_OFF);
    float* partf = (float*)s_raw;             // aliases tile after ctx phase

    if (t < 64) sq[t] = query[(size_t)b * 64 + t];

    // ---- Phase A: action tile -> fp16, XOR-swizzled 16B chunks (DRAM)
    {
        const float4* ga = (const float4*)(act + (size_t)b * nsk * 64);
        int ngroups = nsk * 8;
#pragma unroll 2
        for (int g = t; g < ngroups; g += 128) {
            float4 fa = ga[2 * g];
            float4 fb = ga[2 * g + 1];
            __half2 h0 = __floats2half2_rn(fa.x, fa.y);
            __half2 h1 = __floats2half2_rn(fa.z, fa.w);
            __half2 h2 = __floats2half2_rn(fb.x, fb.y);
            __half2 h3 = __floats2half2_rn(fb.z, fb.w);
            uint4 pk;
            pk.x = *(const unsigned*)&h0;
            pk.y = *(const unsigned*)&h1;
            pk.z = *(const unsigned*)&h2;
            pk.w = *(const unsigned*)&h3;
            unsigned off = ((unsigned)g << 4) ^ ((((unsigned)g >> 3) & 7u) << 4);
            *(uint4*)(sab + off) = pk;
        }
    }
    __syncthreads();

    // ---- Wait for M (hidden: producers finished during our DRAM load)
    if (t == 0) {
        ull target = 4ULL * (gen + 1ULL);
        while (ld_acq(&g_done) < target) __nanosleep(64);
    }
    __syncthreads();

    // ---- W-GEMV: sw[2t],sw[2t+1] = sum_i q[i] * M[i][2t..2t+1]
    {
        ull wp = 0ull;
        const ull* Mp = (const ull*)g_M + t;
#pragma unroll 8
        for (int i = 0; i < 64; i++) {
            float qi = sq[i];
            wp = fma2(pack2(qi, qi), __ldg(Mp + i * 128), wp);
        }
        ((ull*)sw)[t] = wp;
    }
    __syncthreads();

    // ---- Phase B: scores (f32x2). Thread t handles sk = t and sk = t + 128.
    {
        int sk1 = t, sk2 = t + 128;
        bool v2 = sk2 < nsk;
        if (sk1 < nsk) {
            unsigned swb1 = (unsigned)(sk1 * 128) | (((unsigned)sk1 & 7u) << 4);
            unsigned swb2 = (unsigned)(sk2 * 128) | (((unsigned)sk2 & 7u) << 4);
            ull a1[4] = {0, 0, 0, 0}, a2[4] = {0, 0, 0, 0};
#pragma unroll
            for (int i = 0; i < 8; i++) {
                uint4 av1 = *(const uint4*)(sab + (swb1 ^ ((unsigned)i << 4)));
                uint4 av2 = make_uint4(0, 0, 0, 0);
                if (v2) av2 = *(const uint4*)(sab + (swb2 ^ ((unsigned)i << 4)));
                ull d1[4] = {h2f2(av1.x), h2f2(av1.y), h2f2(av1.z), h2f2(av1.w)};
                ull d2[4] = {h2f2(av2.x), h2f2(av2.y), h2f2(av2.z), h2f2(av2.w)};
#pragma unroll
                for (int h = 0; h < 4; h++) {
                    ulonglong2 wA = *(const ulonglong2*)(sw + h * 64 + i * 8);
                    ulonglong2 wB = *(const ulonglong2*)(sw + h * 64 + i * 8 + 4);
                    a1[h] = fma2(d1[0], wA.x, a1[h]);
                    a1[h] = fma2(d1[1], wA.y, a1[h]);
                    a1[h] = fma2(d1[2], wB.x, a1[h]);
                    a1[h] = fma2(d1[3], wB.y, a1[h]);
                    a2[h] = fma2(d2[0], wA.x, a2[h]);
                    a2[h] = fma2(d2[1], wA.y, a2[h]);
                    a2[h] = fma2(d2[2], wB.x, a2[h]);
                    a2[h] = fma2(d2[3], wB.y, a2[h]);
                }
            }
            float s1[4], s2[4];
#pragma unroll
            for (int h = 0; h < 4; h++) {
                float2 f1 = unpack2(a1[h]); s1[h] = f1.x + f1.y;
                float2 f2 = unpack2(a2[h]); s2[h] = f2.x + f2.y;
            }
            scu[0 * SKPAD + sk1] = pack2(s1[0], s1[1]);
            scu[1 * SKPAD + sk1] = pack2(s1[2], s1[3]);
            if (v2) {
                scu[0 * SKPAD + sk2] = pack2(s2[0], s2[1]);
                scu[1 * SKPAD + sk2] = pack2(s2[2], s2[3]);
            }
        }
    }
    __syncthreads();

    // ---- Phase C: softmax, warps 0/1 = head pairs, scores cached in regs
    {
        int wid = t >> 5, lane = t & 31;
        if (wid < 2) {
            int base = wid * SKPAD;
            ull vals[7];
            float mx = -1e30f, my = -1e30f;
#pragma unroll
            for (int r = 0; r < 7; r++) {
                int sk = lane + r * 32;
                vals[r] = (sk < nsk) ? scu[base + sk] : pack2(-1e30f, -1e30f);
                float2 f = unpack2(vals[r]);
                mx = fmaxf(mx, f.x);
                my = fmaxf(my, f.y);
            }
#pragma unroll
            for (int o = 16; o; o >>= 1) {
                mx = fmaxf(mx, __shfl_xor_sync(0xffffffffu, mx, o));
                my = fmaxf(my, __shfl_xor_sync(0xffffffffu, my, o));
            }
            float sx = 0.f, sy = 0.f;
#pragma unroll
            for (int r = 0; r < 7; r++) {
                int sk = lane + r * 32;
                if (sk < nsk) {
                    float2 f = unpack2(vals[r]);
                    float px = __expf(f.x - mx);
                    float py = __expf(f.y - my);
                    sx += px; sy += py;
                    scu[base + sk] = pack2(px, py);
                }
            }
#pragma unroll
            for (int o = 16; o; o >>= 1) {
                sx += __shfl_xor_sync(0xffffffffu, sx, o);
                sy += __shfl_xor_sync(0xffffffffu, sy, o);
            }
            if (lane == 0) {
                sinv[wid * 2]     = 1.f / sx;
                sinv[wid * 2 + 1] = 1.f / sy;
            }
        }
    }
    __syncthreads();

    // ---- Phase D: ctx partials. 128 threads = 16 sk-groups x 8 dim-octets.
    ull acc[16];
    {
        int sg = t >> 3, c8 = t & 7;
#pragma unroll
        for (int v = 0; v < 16; v++) acc[v] = 0ull;
        int chunk = (nsk + 15) >> 4;
        int sk0 = sg * chunk;
        int sk1e = sk0 + chunk; if (sk1e > nsk) sk1e = nsk;
        for (int sk = sk0; sk < sk1e; sk++) {
            unsigned off = (unsigned)(sk * 128) |
                           ((((unsigned)sk & 7u) ^ (unsigned)c8) << 4);
            uint4 av = *(const uint4*)(sab + off);
            ull d0 = h2f2(av.x), d1 = h2f2(av.y), d2 = h2f2(av.z), d3 = h2f2(av.w);
            float2 p01 = unpack2(scu[sk]);
            float2 p23 = unpack2(scu[SKPAD + sk]);
            ull ph0 = pack2(p01.x, p01.x), ph1 = pack2(p01.y, p01.y);
            ull ph2 = pack2(p23.x, p23.x), ph3 = pack2(p23.y, p23.y);
            acc[0]  = fma2(ph0, d0, acc[0]);  acc[1]  = fma2(ph0, d1, acc[1]);
            acc[2]  = fma2(ph0, d2, acc[2]);  acc[3]  = fma2(ph0, d3, acc[3]);
            acc[4]  = fma2(ph1, d0, acc[4]);  acc[5]  = fma2(ph1, d1, acc[5]);
            acc[6]  = fma2(ph1, d2, acc[6]);  acc[7]  = fma2(ph1, d3, acc[7]);
            acc[8]  = fma2(ph2, d0, acc[8]);  acc[9]  = fma2(ph2, d1, acc[9]);
            acc[10] = fma2(ph2, d2, acc[10]); acc[11] = fma2(ph2, d3, acc[11]);
            acc[12] = fma2(ph3, d0, acc[12]); acc[13] = fma2(ph3, d1, acc[13]);
            acc[14] = fma2(ph3, d2, acc[14]); acc[15] = fma2(ph3, d3, acc[15]);
        }
#pragma unroll
        for (int v = 0; v < 16; v++) {
            acc[v] = add2(acc[v], __shfl_xor_sync(0xffffffffu, acc[v], 8));
            acc[v] = add2(acc[v], __shfl_xor_sync(0xffffffffu, acc[v], 16));
        }
    }
    __syncthreads();   // tile reads complete; alias partials over tile

    if ((t & 24) == 0) {
        int w = t >> 5, c8 = t & 7;
        ull* pw = (ull*)partf + w * 128 + c8 * 4;
#pragma unroll
        for (int h = 0; h < 4; h++)
#pragma unroll
            for (int p = 0; p < 4; p++)
                pw[h * 32 + p] = acc[h * 4 + p];
    }
    __syncthreads();

    // ---- Phase E: combine partials -> normalized ctx into sw
    {
        float r0 = partf[t]       + partf[256 + t]       + partf[512 + t]       + partf[768 + t];
        float r1 = partf[t + 128] + partf[256 + t + 128] + partf[512 + t + 128] + partf[768 + t + 128];
        sw[t]       = r0 * sinv[t >> 6];
        sw[t + 128] = r1 * sinv[(t + 128) >> 6];
    }
    __syncthreads();

    // ---- Phase F: out[c] = sum_a ctx[h(c)*64+a] * V[a][c]
    if (t < 64) {
        int c = t, h = t >> 4;
        const ull* cx = (const ull*)(sw + h * 64);
        ull acc2 = 0ull;
#pragma unroll 8
        for (int a = 0; a < 32; a++) {
            float v0 = __ldg(V + (size_t)(2 * a) * 64 + c);
            float v1 = __ldg(V + (size_t)(2 * a + 1) * 64 + c);
            acc2 = fma2(cx[a], pack2(v0, v1), acc2);
        }
        float2 f = unpack2(acc2);
        out[(size_t)b * 64 + c] = f.x + f.y;
    }
}

// ---------------------------------------------------------------------------
extern "C" void kernel_launch(void* const* d_in, const int* in_sizes, int n_in,
                              void* d_out, int out_size) {
    const float* query = (const float*)d_in[0];   // [B,1,64]
    const float* act   = (const float*)d_in[1];   // [B,SK,64]
    const float* Q     = (const float*)d_in[2];   // [64,64]
    const float* K     = (const float*)d_in[3];   // [64,64]
    const float* V     = (const float*)d_in[4];   // [64,64]
    float* out = (float*)d_out;

    int B   = in_sizes[0] / 64;
    int nsk = in_sizes[1] / (B * 64);
    if (nsk > SKPAD) nsk = SKPAD;

    cudaFuncSetAttribute(k_all, cudaFuncAttributeMaxDynamicSharedMemorySize, SMEM_BYTES);

    k_all<<<B + 4, 128, SMEM_BYTES>>>(query, Q, K, act, V, out, nsk, B);
}

// round 12
// speedup vs baseline: 1.1435x; 1.1435x over previous
#include <cuda_runtime.h>
#include <cuda_fp16.h>

#define SKPAD 208
#define MDIM  256
#define BMAX  8192

__device__ float g_W[(size_t)BMAX * MDIM];   // 8 MB scratch

typedef unsigned long long ull;

// ---- packed fp32x2 helpers ----
__device__ __forceinline__ ull fma2(ull a, ull b, ull c) {
    ull d;
    asm("fma.rn.f32x2 %0, %1, %2, %3;" : "=l"(d) : "l"(a), "l"(b), "l"(c));
    return d;
}
__device__ __forceinline__ ull add2(ull a, ull b) {
    ull d;
    asm("add.rn.f32x2 %0, %1, %2;" : "=l"(d) : "l"(a), "l"(b));
    return d;
}
__device__ __forceinline__ ull pack2(float x, float y) {
    ull r;
    asm("mov.b64 %0, {%1, %2};" : "=l"(r) : "f"(x), "f"(y));
    return r;
}
__device__ __forceinline__ float2 unpack2(ull a) {
    float2 f;
    asm("mov.b64 {%0, %1}, %2;" : "=f"(f.x), "=f"(f.y) : "l"(a));
    return f;
}
__device__ __forceinline__ ull h2f2(unsigned h) {
    ull r;
    asm("{\n\t.reg .b16 lo, hi;\n\t.reg .f32 flo, fhi;\n\t"
        "mov.b32 {lo, hi}, %1;\n\t"
        "cvt.f32.f16 flo, lo;\n\tcvt.f32.f16 fhi, hi;\n\t"
        "mov.b64 %0, {flo, fhi};\n\t}" : "=l"(r) : "r"(h));
    return r;
}

// ---------------------------------------------------------------------------
// K1 (fat): 64 batches per CTA, 128 CTAs total (all wave-1).
// Triggers programmatic launch completion at entry so k2 can launch and run
// its DRAM tile-load phase concurrently with k1's execution.
// ---------------------------------------------------------------------------
__global__ __launch_bounds__(256) void k1_w(const float* __restrict__ query,
                                            const float* __restrict__ Qm,
                                            const float* __restrict__ Km, int B) {
    cudaTriggerProgrammaticLaunchCompletion();

    __shared__ float sQ[64 * 64];
    __shared__ float qs[64 * 64];
    __shared__ float sK[64 * 68];
    __shared__ float qp[64 * 64];
    int b0 = blockIdx.x * 64, t = threadIdx.x;

    for (int idx = t; idx < 4096; idx += 256) {
        sQ[idx] = Qm[idx];
        sK[(idx >> 6) * 68 + (idx & 63)] = Km[idx];
        int bb = idx >> 6;
        qs[idx] = (b0 + bb < B) ? query[(size_t)(b0 + bb) * 64 + (idx & 63)] : 0.f;
    }
    __syncthreads();

    {
        int bg = t >> 6, c = t & 63;
        float acc[16];
#pragma unroll
        for (int b = 0; b < 16; b++) acc[b] = 0.f;
#pragma unroll 4
        for (int i4 = 0; i4 < 16; i4++) {
            float q0 = sQ[(i4 * 4 + 0) * 64 + c];
            float q1 = sQ[(i4 * 4 + 1) * 64 + c];
            float q2 = sQ[(i4 * 4 + 2) * 64 + c];
            float q3 = sQ[(i4 * 4 + 3) * 64 + c];
#pragma unroll
            for (int b = 0; b < 16; b++) {
                float4 v = *(const float4*)(qs + (bg * 16 + b) * 64 + i4 * 4);
                acc[b] += v.x * q0 + v.y * q1 + v.z * q2 + v.w * q3;
            }
        }
#pragma unroll
        for (int b = 0; b < 16; b++)
            qp[(bg * 16 + b) * 64 + c] = acc[b];
    }
    __syncthreads();

    {
        int h = t >> 6, a = t & 63;
        const float4* K4 = (const float4*)(sK + a * 68 + h * 16);
        float4 k0 = K4[0], k1 = K4[1], k2 = K4[2], k3 = K4[3];
        int bmax = B - b0; if (bmax > 64) bmax = 64;
        for (int b = 0; b < bmax; b++) {
            const float4* q4 = (const float4*)(qp + b * 64 + h * 16);
            float4 qa = q4[0], qb = q4[1], qc = q4[2], qd = q4[3];
            float wv = qa.x * k0.x + qa.y * k0.y + qa.z * k0.z + qa.w * k0.w
                     + qb.x * k1.x + qb.y * k1.y + qb.z * k1.z + qb.w * k1.w
                     + qc.x * k2.x + qc.y * k2.y + qc.z * k2.z + qc.w * k2.w
                     + qd.x * k3.x + qd.y * k3.y + qd.z * k3.z + qd.w * k3.w;
            g_W[(size_t)(b0 + b) * MDIM + t] = 0.125f * wv;
        }
    }
}

// ---------------------------------------------------------------------------
// K2: R9 attention kernel; g_W read moved AFTER phase A behind a PDL
// grid-dependency sync so phase A overlaps k1's execution.
// ---------------------------------------------------------------------------
#define SA_BYTES   (SKPAD * 128)              // 26624: fp16 swizzled tile (aliased later)
#define SW_OFF     SA_BYTES                   // 1024: W row, later ctx
#define SC_OFF     (SW_OFF + 1024)            // 3328: packed scores ull[2][SKPAD]
#define SINV_OFF   (SC_OFF + 3328)            // 32
#define SMEM_BYTES (SINV_OFF + 32)            // 31008

extern __shared__ char s_raw[];

__global__ __launch_bounds__(128, 7) void k2_fused(const float* __restrict__ act,
                                                   const float* __restrict__ V,
                                                   float* __restrict__ out, int nsk) {
    char*  sab   = s_raw;
    float* sw    = (float*)(s_raw + SW_OFF);
    ull*   scu   = (ull*)(s_raw + SC_OFF);
    float* sinv  = (float*)(s_raw + SINV_OFF);
    float* partf = (float*)s_raw;             // aliases tile after ctx phase

    int b = blockIdx.x;
    int t = threadIdx.x;

    // ---- Phase A: action tile -> fp16, XOR-swizzled 16B chunks (pure DRAM;
    //      overlaps k1 via PDL)
    {
        const float4* ga = (const float4*)(act + (size_t)b * nsk * 64);
        int ngroups = nsk * 8;
#pragma unroll 2
        for (int g = t; g < ngroups; g += 128) {
            float4 fa = ga[2 * g];
            float4 fb = ga[2 * g + 1];
            __half2 h0 = __floats2half2_rn(fa.x, fa.y);
            __half2 h1 = __floats2half2_rn(fa.z, fa.w);
            __half2 h2 = __floats2half2_rn(fb.x, fb.y);
            __half2 h3 = __floats2half2_rn(fb.z, fb.w);
            uint4 pk;
            pk.x = *(const unsigned*)&h0;
            pk.y = *(const unsigned*)&h1;
            pk.z = *(const unsigned*)&h2;
            pk.w = *(const unsigned*)&h3;
            unsigned off = ((unsigned)g << 4) ^ ((((unsigned)g >> 3) & 7u) << 4);
            *(uint4*)(sab + off) = pk;
        }
    }

    // ---- Wait for k1 completion (g_W visible), then load W row
    cudaGridDependencySynchronize();
    sw[t]       = g_W[(size_t)b * MDIM + t];
    sw[t + 128] = g_W[(size_t)b * MDIM + t + 128];
    __syncthreads();

    // ---- Phase B: scores (f32x2). Thread t handles sk = t and sk = t + 128.
    {
        int sk1 = t, sk2 = t + 128;
        bool v2 = sk2 < nsk;
        if (sk1 < nsk) {
            unsigned swb1 = (unsigned)(sk1 * 128) | (((unsigned)sk1 & 7u) << 4);
            unsigned swb2 = (unsigned)(sk2 * 128) | (((unsigned)sk2 & 7u) << 4);
            ull a1[4] = {0, 0, 0, 0}, a2[4] = {0, 0, 0, 0};
#pragma unroll
            for (int i = 0; i < 8; i++) {
                uint4 av1 = *(const uint4*)(sab + (swb1 ^ ((unsigned)i << 4)));
                uint4 av2 = make_uint4(0, 0, 0, 0);
                if (v2) av2 = *(const uint4*)(sab + (swb2 ^ ((unsigned)i << 4)));
                ull d1[4] = {h2f2(av1.x), h2f2(av1.y), h2f2(av1.z), h2f2(av1.w)};
                ull d2[4] = {h2f2(av2.x), h2f2(av2.y), h2f2(av2.z), h2f2(av2.w)};
#pragma unroll
                for (int h = 0; h < 4; h++) {
                    ulonglong2 wA = *(const ulonglong2*)(sw + h * 64 + i * 8);
                    ulonglong2 wB = *(const ulonglong2*)(sw + h * 64 + i * 8 + 4);
                    a1[h] = fma2(d1[0], wA.x, a1[h]);
                    a1[h] = fma2(d1[1], wA.y, a1[h]);
                    a1[h] = fma2(d1[2], wB.x, a1[h]);
                    a1[h] = fma2(d1[3], wB.y, a1[h]);
                    a2[h] = fma2(d2[0], wA.x, a2[h]);
                    a2[h] = fma2(d2[1], wA.y, a2[h]);
                    a2[h] = fma2(d2[2], wB.x, a2[h]);
                    a2[h] = fma2(d2[3], wB.y, a2[h]);
                }
            }
            float s1[4], s2[4];
#pragma unroll
            for (int h = 0; h < 4; h++) {
                float2 f1 = unpack2(a1[h]); s1[h] = f1.x + f1.y;
                float2 f2 = unpack2(a2[h]); s2[h] = f2.x + f2.y;
            }
            scu[0 * SKPAD + sk1] = pack2(s1[0], s1[1]);
            scu[1 * SKPAD + sk1] = pack2(s1[2], s1[3]);
            if (v2) {
                scu[0 * SKPAD + sk2] = pack2(s2[0], s2[1]);
                scu[1 * SKPAD + sk2] = pack2(s2[2], s2[3]);
            }
        }
    }
    __syncthreads();

    // ---- Phase C: softmax, warps 0/1 = head pairs, scores cached in regs
    {
        int wid = t >> 5, lane = t & 31;
        if (wid < 2) {
            int base = wid * SKPAD;
            ull vals[7];
            float mx = -1e30f, my = -1e30f;
#pragma unroll
            for (int r = 0; r < 7; r++) {
                int sk = lane + r * 32;
                vals[r] = (sk < nsk) ? scu[base + sk] : pack2(-1e30f, -1e30f);
                float2 f = unpack2(vals[r]);
                mx = fmaxf(mx, f.x);
                my = fmaxf(my, f.y);
            }
#pragma unroll
            for (int o = 16; o; o >>= 1) {
                mx = fmaxf(mx, __shfl_xor_sync(0xffffffffu, mx, o));
                my = fmaxf(my, __shfl_xor_sync(0xffffffffu, my, o));
            }
            float sx = 0.f, sy = 0.f;
#pragma unroll
            for (int r = 0; r < 7; r++) {
                int sk = lane + r * 32;
                if (sk < nsk) {
                    float2 f = unpack2(vals[r]);
                    float px = __expf(f.x - mx);
                    float py = __expf(f.y - my);
                    sx += px; sy += py;
                    scu[base + sk] = pack2(px, py);
                }
            }
#pragma unroll
            for (int o = 16; o; o >>= 1) {
                sx += __shfl_xor_sync(0xffffffffu, sx, o);
                sy += __shfl_xor_sync(0xffffffffu, sy, o);
            }
            if (lane == 0) {
                sinv[wid * 2]     = 1.f / sx;
                sinv[wid * 2 + 1] = 1.f / sy;
            }
        }
    }
    __syncthreads();

    // ---- Phase D: ctx partials. 128 threads = 16 sk-groups x 8 dim-octets.
    ull acc[16];
    {
        int sg = t >> 3, c8 = t & 7;
#pragma unroll
        for (int v = 0; v < 16; v++) acc[v] = 0ull;
        int chunk = (nsk + 15) >> 4;
        int sk0 = sg * chunk;
        int sk1e = sk0 + chunk; if (sk1e > nsk) sk1e = nsk;
        for (int sk = sk0; sk < sk1e; sk++) {
            unsigned off = (unsigned)(sk * 128) |
                           ((((unsigned)sk & 7u) ^ (unsigned)c8) << 4);
            uint4 av = *(const uint4*)(sab + off);
            ull d0 = h2f2(av.x), d1 = h2f2(av.y), d2 = h2f2(av.z), d3 = h2f2(av.w);
            float2 p01 = unpack2(scu[sk]);
            float2 p23 = unpack2(scu[SKPAD + sk]);
            ull ph0 = pack2(p01.x, p01.x), ph1 = pack2(p01.y, p01.y);
            ull ph2 = pack2(p23.x, p23.x), ph3 = pack2(p23.y, p23.y);
            acc[0]  = fma2(ph0, d0, acc[0]);  acc[1]  = fma2(ph0, d1, acc[1]);
            acc[2]  = fma2(ph0, d2, acc[2]);  acc[3]  = fma2(ph0, d3, acc[3]);
            acc[4]  = fma2(ph1, d0, acc[4]);  acc[5]  = fma2(ph1, d1, acc[5]);
            acc[6]  = fma2(ph1, d2, acc[6]);  acc[7]  = fma2(ph1, d3, acc[7]);
            acc[8]  = fma2(ph2, d0, acc[8]);  acc[9]  = fma2(ph2, d1, acc[9]);
            acc[10] = fma2(ph2, d2, acc[10]); acc[11] = fma2(ph2, d3, acc[11]);
            acc[12] = fma2(ph3, d0, acc[12]); acc[13] = fma2(ph3, d1, acc[13]);
            acc[14] = fma2(ph3, d2, acc[14]); acc[15] = fma2(ph3, d3, acc[15]);
        }
#pragma unroll
        for (int v = 0; v < 16; v++) {
            acc[v] = add2(acc[v], __shfl_xor_sync(0xffffffffu, acc[v], 8));
            acc[v] = add2(acc[v], __shfl_xor_sync(0xffffffffu, acc[v], 16));
        }
    }
    __syncthreads();   // tile reads complete; alias partials over tile

    if ((t & 24) == 0) {
        int w = t >> 5, c8 = t & 7;
        ull* pw = (ull*)partf + w * 128 + c8 * 4;
#pragma unroll
        for (int h = 0; h < 4; h++)
#pragma unroll
            for (int p = 0; p < 4; p++)
                pw[h * 32 + p] = acc[h * 4 + p];
    }
    __syncthreads();

    // ---- Phase E: combine partials -> normalized ctx into sw
    {
        float r0 = partf[t]       + partf[256 + t]       + partf[512 + t]       + partf[768 + t];
        float r1 = partf[t + 128] + partf[256 + t + 128] + partf[512 + t + 128] + partf[768 + t + 128];
        sw[t]       = r0 * sinv[t >> 6];
        sw[t + 128] = r1 * sinv[(t + 128) >> 6];
    }
    __syncthreads();

    // ---- Phase F: out[c] = sum_a ctx[h(c)*64+a] * V[a][c]
    if (t < 64) {
        int c = t, h = t >> 4;
        const ull* cx = (const ull*)(sw + h * 64);
        ull acc2 = 0ull;
#pragma unroll 8
        for (int a = 0; a < 32; a++) {
            float v0 = __ldg(V + (size_t)(2 * a) * 64 + c);
            float v1 = __ldg(V + (size_t)(2 * a + 1) * 64 + c);
            acc2 = fma2(cx[a], pack2(v0, v1), acc2);
        }
        float2 f = unpack2(acc2);
        out[(size_t)b * 64 + c] = f.x + f.y;
    }
}

// ---------------------------------------------------------------------------
extern "C" void kernel_launch(void* const* d_in, const int* in_sizes, int n_in,
                              void* d_out, int out_size) {
    const float* query = (const float*)d_in[0];   // [B,1,64]
    const float* act   = (const float*)d_in[1];   // [B,SK,64]
    const float* Q     = (const float*)d_in[2];   // [64,64]
    const float* K     = (const float*)d_in[3];   // [64,64]
    const float* V     = (const float*)d_in[4];   // [64,64]
    float* out = (float*)d_out;

    int B   = in_sizes[0] / 64;
    int nsk = in_sizes[1] / (B * 64);
    if (nsk > SKPAD) nsk = SKPAD;

    cudaFuncSetAttribute(k2_fused, cudaFuncAttributeMaxDynamicSharedMemorySize, SMEM_BYTES);

    k1_w<<<(B + 63) / 64, 256>>>(query, Q, K, B);

    // k2 with programmatic dependent launch: starts while k1 runs; its phase A
    // needs no g_W, and cudaGridDependencySynchronize() gates the W read.
    cudaLaunchConfig_t cfg = {};
    cfg.gridDim = dim3((unsigned)B, 1, 1);
    cfg.blockDim = dim3(128, 1, 1);
    cfg.dynamicSmemBytes = SMEM_BYTES;
    cfg.stream = 0;
    cudaLaunchAttribute attrs[1];
    attrs[0].id = cudaLaunchAttributeProgrammaticStreamSerialization;
    attrs[0].val.programmaticStreamSerializationAllowed = 1;
    cfg.attrs = attrs;
    cfg.numAttrs = 1;
    cudaLaunchKernelEx(&cfg, k2_fused, act, V, out, nsk);
}